// round 12
// baseline (speedup 1.0000x reference)
#include <cuda_runtime.h>
#include <cstdint>
#include <math.h>

#define BATCH 2048
#define NIN   512
#define NOUT  512
#define PLA ((size_t)BATCH * NIN)
#define PLB ((size_t)NOUT * NIN)

// ---------------- device scratch ----------------
// "Atom" plane layout:
//  plane = tiles of 128 rows x 32 k (4096 floats, 16KB), tile idx = (k>>5)*nR + (row>>7)
//  tile  = atoms of 8 rows x 16 k (128 floats), atom idx = ((row&127)>>3)*2 + ((k&31)>>4)
//  atom  = float off ((row&7)*4 + (k&3))*4 + ((k>>2)&3)
__device__ float g_XP[8 * BATCH * NIN];     // x planes (atom, nR=16), tf32
__device__ float g_ZP[44 * BATCH * NIN];    // pair channels (atom, nR=16), tf32
__device__ float g_XR[8 * BATCH * NIN];     // xr (atom, nR=16), fp32
__device__ float g_OUTP[8 * BATCH * NOUT];  // planar LINEAR output
__device__ float g_WR[4 * NIN * NIN];       // w_right (atom, nR=4), tf32
__device__ float g_WL[4 * NOUT * NIN];      // w_left (atom, nR=4), tf32
__device__ float g_WT[20 * NOUT * NIN];     // weight paths (atom, nR=4), tf32

__constant__ int c_grade[8] = {0,1,1,1,2,2,2,3};
__constant__ int c_nch[8] = {5,7,7,7,7,7,7,5};
__constant__ int c_zord[8] = {1,2,3,4,5,6,0,7};   // long blades first
__constant__ int c_aidx[8][7] = {
    {0, 8,16,30,44, 0, 0},
    {1, 9,17,20,31,34,45},
    {2,10,18,21,32,35,46},
    {3,11,19,22,33,36,47},
    {4,12,23,26,37,40,48},
    {5,13,24,27,38,41,49},
    {6,14,25,28,39,42,50},
    {7,15,29,43,51, 0, 0}
};
__constant__ int c_bidx[8][7] = {
    {0, 4, 8,14,20, 0, 0},
    {1, 5, 9,10,15,16,21},
    {1, 5, 9,10,15,16,21},
    {1, 5, 9,10,15,16,21},
    {2, 6,11,12,17,18,22},
    {2, 6,11,12,17,18,22},
    {2, 6,11,12,17,18,22},
    {3, 7,13,19,23, 0, 0}
};

// ---------------- helpers ----------------
__device__ __forceinline__ float rtf(float x) {
    uint32_t u;
    asm("cvt.rna.tf32.f32 %0, %1;" : "=r"(u) : "f"(x));
    return __uint_as_float(u);
}
__device__ __forceinline__ uint32_t smem_u32(const void* p) {
    uint32_t a;
    asm("{ .reg .u64 t; cvta.to.shared.u64 t, %1; cvt.u32.u64 %0, t; }" : "=r"(a) : "l"(p));
    return a;
}
__device__ __forceinline__ void mbar_init(uint32_t a, uint32_t cnt) {
    asm volatile("mbarrier.init.shared.b64 [%0], %1;" :: "r"(a), "r"(cnt) : "memory");
}
__device__ __forceinline__ void mbar_expect(uint32_t a, uint32_t tx) {
    asm volatile("mbarrier.arrive.expect_tx.shared.b64 _, [%0], %1;" :: "r"(a), "r"(tx) : "memory");
}
__device__ __forceinline__ void mbar_arrive(uint32_t a) {
    asm volatile("mbarrier.arrive.shared.b64 _, [%0];" :: "r"(a) : "memory");
}
__device__ __forceinline__ void mbar_wait(uint32_t mbar, uint32_t parity) {
    asm volatile(
        "{\n\t.reg .pred P;\n\t"
        "WL_%=:\n\t"
        "mbarrier.try_wait.parity.acquire.cta.shared::cta.b64 P, [%0], %1, 0x989680;\n\t"
        "@P bra.uni WD_%=;\n\t"
        "bra.uni WL_%=;\n\t"
        "WD_%=:\n\t}"
        :: "r"(mbar), "r"(parity) : "memory");
}
__device__ __forceinline__ void bulk_g2s(uint32_t dst, const float* src, uint32_t bytes, uint32_t mbar) {
    asm volatile(
        "cp.async.bulk.shared::cluster.global.mbarrier::complete_tx::bytes [%0], [%1], %2, [%3];"
        :: "r"(dst), "l"(src), "r"(bytes), "r"(mbar) : "memory");
}
__device__ __forceinline__ void mma_tf32(float* c, uint32_t a0, uint32_t a1, uint32_t a2, uint32_t a3,
                                         uint32_t b0, uint32_t b1) {
    asm volatile(
        "mma.sync.aligned.m16n8k8.row.col.f32.tf32.tf32.f32 "
        "{%0,%1,%2,%3}, {%4,%5,%6,%7}, {%8,%9}, {%0,%1,%2,%3};"
        : "+f"(c[0]), "+f"(c[1]), "+f"(c[2]), "+f"(c[3])
        : "r"(a0), "r"(a1), "r"(a2), "r"(a3), "r"(b0), "r"(b1));
}
#define FENCE_ASYNC() asm volatile("fence.proxy.async.shared::cta;" ::: "memory")

__device__ __forceinline__ size_t qbase(int r, int group, int X, int nR) {
    return ((size_t)((group >> 1) * nR + (r >> 7))) * 4096
         + (size_t)((((r & 127) >> 3) * 2 + (group & 1)) * 128 + ((r & 7) * 4 + X) * 4);
}

// ---------------- K0: transpose + tf32-round inputs into atom planes ----------------
__global__ void k0_prep(const float* __restrict__ x,
                        const float* __restrict__ weight,
                        const float* __restrict__ w_right,
                        const float* __restrict__ w_left) {
    int idx = blockIdx.x * blockDim.x + threadIdx.x;   // BATCH*128
    int b = idx >> 7;
    int j = idx & 127;
    int group = j >> 2, X = j & 3;
    int k0v = group * 16 + X;

    float xb[8][4];
    #pragma unroll
    for (int t = 0; t < 4; t++) {
        int k = k0v + 4 * t;
        const float4* p = (const float4*)(x + ((size_t)b * 512 + k) * 8);
        float4 f0 = p[0], f1 = p[1];
        xb[0][t] = f0.x; xb[1][t] = f0.y; xb[2][t] = f0.z; xb[3][t] = f0.w;
        xb[4][t] = f1.x; xb[5][t] = f1.y; xb[6][t] = f1.z; xb[7][t] = f1.w;
    }
    size_t xo = qbase(b, group, X, 16);
    #pragma unroll
    for (int bl = 0; bl < 8; bl++) {
        float4 o = make_float4(rtf(xb[bl][0]), rtf(xb[bl][1]), rtf(xb[bl][2]), rtf(xb[bl][3]));
        *(float4*)(g_XP + (size_t)bl * PLA + xo) = o;
    }

    if (b < NOUT) {
        int m = b;
        size_t wo = qbase(m, group, X, 4);
        float wr[4][4], wl[4][4], wt[20][4];
        #pragma unroll
        for (int t = 0; t < 4; t++) {
            int k = k0v + 4 * t;
            float4 r = ((const float4*)w_right)[(size_t)m * 512 + k];
            wr[0][t] = r.x; wr[1][t] = r.y; wr[2][t] = r.z; wr[3][t] = r.w;
            float4 l = ((const float4*)w_left)[(size_t)m * 512 + k];
            wl[0][t] = l.x; wl[1][t] = l.y; wl[2][t] = l.z; wl[3][t] = l.w;
            const float4* wp = (const float4*)(weight + ((size_t)m * 512 + k) * 20);
            #pragma unroll
            for (int q = 0; q < 5; q++) {
                float4 f = wp[q];
                wt[q*4+0][t] = f.x; wt[q*4+1][t] = f.y; wt[q*4+2][t] = f.z; wt[q*4+3][t] = f.w;
            }
        }
        #pragma unroll
        for (int g = 0; g < 4; g++) {
            float4 o = make_float4(rtf(wr[g][0]), rtf(wr[g][1]), rtf(wr[g][2]), rtf(wr[g][3]));
            *(float4*)(g_WR + (size_t)g * PLB + wo) = o;
            float4 p = make_float4(rtf(wl[g][0]), rtf(wl[g][1]), rtf(wl[g][2]), rtf(wl[g][3]));
            *(float4*)(g_WL + (size_t)g * PLB + wo) = p;
        }
        #pragma unroll
        for (int q = 0; q < 20; q++) {
            float4 o = make_float4(rtf(wt[q][0]), rtf(wt[q][1]), rtf(wt[q][2]), rtf(wt[q][3]));
            *(float4*)(g_WT + (size_t)q * PLB + wo) = o;
        }
    }
}

// ---------------- tensor-core GEMM: bulk ring, unroll-by-3 (const slot offsets) ----------------
#define STAGE_F 8192                     // A 4096 + B 4096 floats per slot
#define STAGE_BYTES (STAGE_F * 4)
#define SMEM_BYTES (3 * STAGE_BYTES)     // 98304

__global__ void __launch_bounds__(256, 2) gemm_mma(int mode, const float* __restrict__ b_left) {
    extern __shared__ __align__(128) float sm[];
    __shared__ __align__(8) unsigned long long bars[6];   // full0..2, empty0..2

    uint32_t sbase = smem_u32(sm);
    uint32_t barb  = smem_u32(bars);

    int tid = threadIdx.x;
    int z  = c_zord[blockIdx.z];
    int mt = blockIdx.y;
    int nt = blockIdx.x;
    int m0 = mt * 128, n0 = nt * 128;

    int nch = (mode == 0) ? 1 : c_nch[z];
    int n_iter = nch << 4;

    int wid = tid >> 5, lane = tid & 31;
    int rb = (wid >> 1) * 32;
    int cb = (wid & 1) * 64;
    int grp = lane >> 2, tg = lane & 3;

    if (tid == 0) {
        #pragma unroll
        for (int s = 0; s < 3; s++) {
            mbar_init(barb + s * 8, 1);        // full: tx-based
            mbar_init(barb + 24 + s * 8, 8);   // empty: one arrive per warp
        }
        FENCE_ASYNC();
    }
    __syncthreads();

    float acc[2][8][4];
    #pragma unroll
    for (int mi = 0; mi < 2; mi++)
        #pragma unroll
        for (int ni = 0; ni < 8; ni++)
            #pragma unroll
            for (int q = 0; q < 4; q++) acc[mi][ni][q] = 0.f;

    // ---- producer state (tid 0 only) ----
    const float* pA = nullptr;
    const float* pB = nullptr;
    int pch = 0, pq = 0;
    auto setch = [&](int ch) {
        if (mode == 0) {
            pA = g_XP + (size_t)z * PLA;
            pB = g_WR + (size_t)c_grade[z] * PLB;
        } else {
            int ai = c_aidx[z][ch], bi = c_bidx[z][ch];
            pA = (ai < 8) ? g_XP + (size_t)ai * PLA : g_ZP + (size_t)(ai - 8) * PLA;
            pB = (bi < 4) ? g_WL + (size_t)bi * PLB : g_WT + (size_t)(bi - 4) * PLB;
        }
        pA += (size_t)mt * 4096;
        pB += (size_t)nt * 4096;
    };
    auto advance = [&]() {
        pA += 65536;            // next k-chunk: A stride 16 tiles
        pB += 16384;            // next k-chunk: B stride 4 tiles
        if (++pq == 16) { pq = 0; if (++pch < nch) setch(pch); }
    };

    if (tid == 0) {
        setch(0);
        #pragma unroll
        for (int s = 0; s < 3; s++) {
            uint32_t fb = barb + s * 8;
            mbar_expect(fb, 32768);
            bulk_g2s(sbase + s * STAGE_BYTES, pA, 16384, fb);
            bulk_g2s(sbase + s * STAGE_BYTES + 16384, pB, 16384, fb);
            advance();
        }
    }

    int fl = grp * 16 + tg * 4;
    int artA = rb >> 3;
    int brt  = cb >> 3;

    // one pipeline body; slot is a literal -> all addresses compile-time offsets
    auto do_stage = [&](int i, int slot, int par) {
        const float* At = sm + slot * STAGE_F;         // constant-folded per call site
        const float* Bt = At + 4096;
        uint32_t fullb  = barb + slot * 8;
        uint32_t emptyb = barb + 24 + slot * 8;

        mbar_wait(fullb, par);                          // all lanes (try_wait sleeps)

        #pragma unroll
        for (int kc = 0; kc < 2; kc++) {
            float4 fa[2][2];
            #pragma unroll
            for (int mi = 0; mi < 2; mi++) {
                int ar0 = artA + mi * 2;
                fa[mi][0] = *(const float4*)(At + (ar0 * 2 + kc) * 128 + fl);
                fa[mi][1] = *(const float4*)(At + ((ar0 + 1) * 2 + kc) * 128 + fl);
            }
            float4 fb[8];
            #pragma unroll
            for (int ni = 0; ni < 8; ni++)
                fb[ni] = *(const float4*)(Bt + ((brt + ni) * 2 + kc) * 128 + fl);
            #pragma unroll
            for (int mi = 0; mi < 2; mi++)
                #pragma unroll
                for (int ni = 0; ni < 8; ni++) {
                    mma_tf32(acc[mi][ni],
                             __float_as_uint(fa[mi][0].x), __float_as_uint(fa[mi][1].x),
                             __float_as_uint(fa[mi][0].y), __float_as_uint(fa[mi][1].y),
                             __float_as_uint(fb[ni].x), __float_as_uint(fb[ni].y));
                    mma_tf32(acc[mi][ni],
                             __float_as_uint(fa[mi][0].z), __float_as_uint(fa[mi][1].z),
                             __float_as_uint(fa[mi][0].w), __float_as_uint(fa[mi][1].w),
                             __float_as_uint(fb[ni].z), __float_as_uint(fb[ni].w));
                }
        }

        if (lane == 0) mbar_arrive(emptyb);             // warp-done with slot

        if (tid == 0 && i + 3 < n_iter) {               // refill slot with stage i+3
            mbar_wait(emptyb, par);
            mbar_expect(fullb, 32768);
            bulk_g2s(sbase + slot * STAGE_BYTES, pA, 16384, fullb);
            bulk_g2s(sbase + slot * STAGE_BYTES + 16384, pB, 16384, fullb);
            advance();
        }
    };

    int par = 0;
    for (int i = 0; i < n_iter; i += 3) {
        do_stage(i, 0, par);
        if (i + 1 < n_iter) do_stage(i + 1, 1, par);
        if (i + 2 < n_iter) do_stage(i + 2, 2, par);
        par ^= 1;
    }

    // ---------------- epilogue ----------------
    const float RS2 = 0.70710678118654752440f;
    if (mode == 0) {
        __syncthreads();
        #pragma unroll
        for (int mi = 0; mi < 2; mi++)
            #pragma unroll
            for (int h = 0; h < 2; h++) {
                int r = rb + mi * 16 + grp + h * 8;
                int rpart = ((r >> 3) * 2) * 128 + (r & 7) * 16;
                #pragma unroll
                for (int ni = 0; ni < 8; ni++) {
                    int c = cb + ni * 8 + 2 * tg;
                    #pragma unroll
                    for (int d = 0; d < 2; d++) {
                        int cc = c + d;
                        int off = (cc >> 5) * 4096 + rpart + ((cc >> 4) & 1) * 128
                                + (cc & 3) * 4 + ((cc >> 2) & 3);
                        sm[off] = acc[mi][ni][h * 2 + d];
                    }
                }
            }
        __syncthreads();
        float* XRp = g_XR + (size_t)z * PLA + ((size_t)(nt * 4) * 16 + mt) * 4096;
        #pragma unroll
        for (int t = 0; t < 4; t++) {
            float* dst = XRp + (size_t)t * 65536;
            const float* src = sm + t * 4096;
            #pragma unroll
            for (int r = 0; r < 4; r++) {
                int e = tid + (r << 8);
                *(float4*)(dst + e * 4) = *(const float4*)(src + e * 4);
            }
        }
    } else {
        float* Out = g_OUTP + (size_t)z * PLA;
        #pragma unroll
        for (int mi = 0; mi < 2; mi++)
            #pragma unroll
            for (int h = 0; h < 2; h++) {
                int row = m0 + rb + mi * 16 + grp + h * 8;
                float* dp = Out + (size_t)row * NOUT + n0 + cb;
                #pragma unroll
                for (int ni = 0; ni < 8; ni++) {
                    int col = ni * 8 + 2 * tg;
                    float v0 = acc[mi][ni][h * 2 + 0];
                    float v1 = acc[mi][ni][h * 2 + 1];
                    if (z == 0) {
                        v0 += b_left[n0 + cb + col];
                        v1 += b_left[n0 + cb + col + 1];
                    }
                    *(float2*)(dp + col) = make_float2(v0 * RS2, v1 * RS2);
                }
            }
    }
}

// ---------------- K2: gating + 44 pair channels (atom quads in/out) ----------------
__global__ void k2_pair(const float* __restrict__ norm_a) {
    int idx = blockIdx.x * blockDim.x + threadIdx.x;   // BATCH*128
    int b = idx >> 7;
    int j = idx & 127;
    int group = j >> 2, X = j & 3;
    int k0v = group * 16 + X;

    size_t qo = qbase(b, group, X, 16);
    float xv[8][4], yv[8][4];
    #pragma unroll
    for (int bl = 0; bl < 8; bl++) {
        float4 fx = *(const float4*)(g_XP + (size_t)bl * PLA + qo);
        xv[bl][0] = fx.x; xv[bl][1] = fx.y; xv[bl][2] = fx.z; xv[bl][3] = fx.w;
        float4 fy = *(const float4*)(g_XR + (size_t)bl * PLA + qo);
        yv[bl][0] = fy.x; yv[bl][1] = fy.y; yv[bl][2] = fy.z; yv[bl][3] = fy.w;
    }

    #pragma unroll
    for (int t = 0; t < 4; t++) {
        int n = k0v + 4 * t;
        float4 na = *(const float4*)(norm_a + n * 4);
        float n0 = fabsf(yv[0][t]);
        float n1 = sqrtf(yv[1][t]*yv[1][t] + yv[2][t]*yv[2][t] + yv[3][t]*yv[3][t]);
        float n2 = sqrtf(yv[4][t]*yv[4][t] + yv[5][t]*yv[5][t] + yv[6][t]*yv[6][t]);
        float n3 = fabsf(yv[7][t]);
        float s0 = 1.f / (1.f + expf(-na.x));
        float s1 = 1.f / (1.f + expf(-na.y));
        float s2 = 1.f / (1.f + expf(-na.z));
        float s3 = 1.f / (1.f + expf(-na.w));
        float i0 = 1.f / (s0 * (n0 - 1.f) + 1.f + 1e-6f);
        float i1 = 1.f / (s1 * (n1 - 1.f) + 1.f + 1e-6f);
        float i2 = 1.f / (s2 * (n2 - 1.f) + 1.f + 1e-6f);
        float i3 = 1.f / (s3 * (n3 - 1.f) + 1.f + 1e-6f);
        yv[0][t] *= i0;
        yv[1][t] *= i1; yv[2][t] *= i1; yv[3][t] *= i1;
        yv[4][t] *= i2; yv[5][t] *= i2; yv[6][t] *= i2;
        yv[7][t] *= i3;
    }

    auto emit = [&](int c, auto f) {
        float4 o = make_float4(rtf(f(0)), rtf(f(1)), rtf(f(2)), rtf(f(3)));
        *(float4*)(g_ZP + (size_t)c * PLA + qo) = o;
    };
    emit(0,  [&](int t){ return xv[0][t]*yv[0][t]; });
    emit(1,  [&](int t){ return xv[0][t]*yv[1][t]; });
    emit(2,  [&](int t){ return xv[0][t]*yv[2][t]; });
    emit(3,  [&](int t){ return xv[0][t]*yv[3][t]; });
    emit(4,  [&](int t){ return xv[0][t]*yv[4][t]; });
    emit(5,  [&](int t){ return xv[0][t]*yv[5][t]; });
    emit(6,  [&](int t){ return xv[0][t]*yv[6][t]; });
    emit(7,  [&](int t){ return xv[0][t]*yv[7][t]; });
    emit(8,  [&](int t){ return xv[1][t]*yv[1][t] + xv[2][t]*yv[2][t] + xv[3][t]*yv[3][t]; });
    emit(9,  [&](int t){ return xv[1][t]*yv[0][t]; });
    emit(10, [&](int t){ return xv[2][t]*yv[0][t]; });
    emit(11, [&](int t){ return xv[3][t]*yv[0][t]; });
    emit(12, [&](int t){ return -xv[2][t]*yv[4][t] - xv[3][t]*yv[5][t]; });
    emit(13, [&](int t){ return  xv[1][t]*yv[4][t] - xv[3][t]*yv[6][t]; });
    emit(14, [&](int t){ return  xv[1][t]*yv[5][t] + xv[2][t]*yv[6][t]; });
    emit(15, [&](int t){ return  xv[1][t]*yv[2][t] - xv[2][t]*yv[1][t]; });
    emit(16, [&](int t){ return  xv[1][t]*yv[3][t] - xv[3][t]*yv[1][t]; });
    emit(17, [&](int t){ return  xv[2][t]*yv[3][t] - xv[3][t]*yv[2][t]; });
    emit(18, [&](int t){ return  xv[3][t]*yv[7][t]; });
    emit(19, [&](int t){ return -xv[2][t]*yv[7][t]; });
    emit(20, [&](int t){ return  xv[1][t]*yv[7][t]; });
    emit(21, [&](int t){ return  xv[1][t]*yv[6][t] - xv[2][t]*yv[5][t] + xv[3][t]*yv[4][t]; });
    emit(22, [&](int t){ return -(xv[4][t]*yv[4][t] + xv[5][t]*yv[5][t] + xv[6][t]*yv[6][t]); });
    emit(23, [&](int t){ return  xv[4][t]*yv[2][t] + xv[5][t]*yv[3][t]; });
    emit(24, [&](int t){ return -xv[4][t]*yv[1][t] + xv[6][t]*yv[3][t]; });
    emit(25, [&](int t){ return -xv[5][t]*yv[1][t] - xv[6][t]*yv[2][t]; });
    emit(26, [&](int t){ return -xv[6][t]*yv[7][t]; });
    emit(27, [&](int t){ return  xv[5][t]*yv[7][t]; });
    emit(28, [&](int t){ return -xv[4][t]*yv[7][t]; });
    emit(29, [&](int t){ return  xv[4][t]*yv[0][t]; });
    emit(30, [&](int t){ return  xv[5][t]*yv[0][t]; });
    emit(31, [&](int t){ return  xv[6][t]*yv[0][t]; });
    emit(32, [&](int t){ return -xv[5][t]*yv[6][t] + xv[6][t]*yv[5][t]; });
    emit(33, [&](int t){ return  xv[4][t]*yv[6][t] - xv[6][t]*yv[4][t]; });
    emit(34, [&](int t){ return -xv[4][t]*yv[5][t] + xv[5][t]*yv[4][t]; });
    emit(35, [&](int t){ return  xv[4][t]*yv[3][t] - xv[5][t]*yv[2][t] + xv[6][t]*yv[1][t]; });
    emit(36, [&](int t){ return -xv[7][t]*yv[7][t]; });
    emit(37, [&](int t){ return -xv[7][t]*yv[6][t]; });
    emit(38, [&](int t){ return  xv[7][t]*yv[5][t]; });
    emit(39, [&](int t){ return -xv[7][t]*yv[4][t]; });
    emit(40, [&](int t){ return  xv[7][t]*yv[3][t]; });
    emit(41, [&](int t){ return -xv[7][t]*yv[2][t]; });
    emit(42, [&](int t){ return  xv[7][t]*yv[1][t]; });
    emit(43, [&](int t){ return  xv[7][t]*yv[0][t]; });
}

// ---------------- K4: planar -> interleaved output ----------------
__global__ void k4_out(float* __restrict__ out) {
    int idx = blockIdx.x * blockDim.x + threadIdx.x;   // BATCH*NOUT
    size_t o = (size_t)idx;
    float4 o0, o1;
    o0.x = g_OUTP[0*PLA + o]; o0.y = g_OUTP[1*PLA + o];
    o0.z = g_OUTP[2*PLA + o]; o0.w = g_OUTP[3*PLA + o];
    o1.x = g_OUTP[4*PLA + o]; o1.y = g_OUTP[5*PLA + o];
    o1.z = g_OUTP[6*PLA + o]; o1.w = g_OUTP[7*PLA + o];
    ((float4*)out)[o * 2 + 0] = o0;
    ((float4*)out)[o * 2 + 1] = o1;
}

// ---------------- launch ----------------
extern "C" void kernel_launch(void* const* d_in, const int* in_sizes, int n_in,
                              void* d_out, int out_size) {
    const float* x       = (const float*)d_in[0];
    const float* weight  = (const float*)d_in[1];
    const float* w_right = (const float*)d_in[2];
    const float* w_left  = (const float*)d_in[3];
    const float* b_left  = (const float*)d_in[4];
    const float* norm_a  = (const float*)d_in[5];
    float* out = (float*)d_out;

    cudaFuncSetAttribute(gemm_mma, cudaFuncAttributeMaxDynamicSharedMemorySize, SMEM_BYTES);

    int eb = (BATCH * 128) / 256;
    k0_prep<<<eb, 256>>>(x, weight, w_right, w_left);

    dim3 gg(NOUT / 128, BATCH / 128, 8);
    gemm_mma<<<gg, 256, SMEM_BYTES>>>(0, nullptr);
    k2_pair<<<eb, 256>>>(norm_a);
    gemm_mma<<<gg, 256, SMEM_BYTES>>>(1, b_left);
    k4_out<<<(BATCH * NOUT) / 256, 256>>>(out);
}

// round 16
// speedup vs baseline: 1.1730x; 1.1730x over previous
#include <cuda_runtime.h>
#include <cstdint>
#include <math.h>

#define BATCH 2048
#define NIN   512
#define NOUT  512
#define PLA ((size_t)BATCH * NIN)
#define PLB ((size_t)NOUT * NIN)

// ---------------- device scratch ----------------
// "Atom" plane layout:
//  plane = tiles of 128 rows x 32 k (4096 floats, 16KB), tile idx = (k>>5)*nR + (row>>7)
//  tile  = atoms of 8 rows x 16 k (128 floats), atom idx = ((row&127)>>3)*2 + ((k&31)>>4)
//  atom  = float off ((row&7)*4 + (k&3))*4 + ((k>>2)&3)
__device__ float g_XP[8 * BATCH * NIN];     // x planes (atom, nR=16), tf32
__device__ float g_ZP[44 * BATCH * NIN];    // pair channels (atom, nR=16), tf32
__device__ float g_XR[8 * BATCH * NIN];     // xr (atom, nR=16), fp32
__device__ float g_OUTP[8 * BATCH * NOUT];  // planar LINEAR output
__device__ float g_WR[4 * NIN * NIN];       // w_right (atom, nR=4), tf32
__device__ float g_WL[4 * NOUT * NIN];      // w_left (atom, nR=4), tf32
__device__ float g_WT[20 * NOUT * NIN];     // weight paths (atom, nR=4), tf32

__constant__ int c_grade[8] = {0,1,1,1,2,2,2,3};
__constant__ int c_nch[8] = {5,7,7,7,7,7,7,5};
__constant__ int c_zord[8] = {1,2,3,4,5,6,0,7};   // long blades first
__constant__ int c_aidx[8][7] = {
    {0, 8,16,30,44, 0, 0},
    {1, 9,17,20,31,34,45},
    {2,10,18,21,32,35,46},
    {3,11,19,22,33,36,47},
    {4,12,23,26,37,40,48},
    {5,13,24,27,38,41,49},
    {6,14,25,28,39,42,50},
    {7,15,29,43,51, 0, 0}
};
__constant__ int c_bidx[8][7] = {
    {0, 4, 8,14,20, 0, 0},
    {1, 5, 9,10,15,16,21},
    {1, 5, 9,10,15,16,21},
    {1, 5, 9,10,15,16,21},
    {2, 6,11,12,17,18,22},
    {2, 6,11,12,17,18,22},
    {2, 6,11,12,17,18,22},
    {3, 7,13,19,23, 0, 0}
};

// ---------------- helpers ----------------
__device__ __forceinline__ float rtf(float x) {
    uint32_t u;
    asm("cvt.rna.tf32.f32 %0, %1;" : "=r"(u) : "f"(x));
    return __uint_as_float(u);
}
__device__ __forceinline__ uint32_t smem_u32(const void* p) {
    uint32_t a;
    asm("{ .reg .u64 t; cvta.to.shared.u64 t, %1; cvt.u32.u64 %0, t; }" : "=r"(a) : "l"(p));
    return a;
}
__device__ __forceinline__ void mbar_init(uint32_t a, uint32_t cnt) {
    asm volatile("mbarrier.init.shared.b64 [%0], %1;" :: "r"(a), "r"(cnt) : "memory");
}
__device__ __forceinline__ void mbar_expect(uint32_t a, uint32_t tx) {
    asm volatile("mbarrier.arrive.expect_tx.shared.b64 _, [%0], %1;" :: "r"(a), "r"(tx) : "memory");
}
__device__ __forceinline__ void mbar_arrive(uint32_t a) {
    asm volatile("mbarrier.arrive.shared.b64 _, [%0];" :: "r"(a) : "memory");
}
__device__ __forceinline__ void mbar_wait(uint32_t mbar, uint32_t parity) {
    asm volatile(
        "{\n\t.reg .pred P;\n\t"
        "WL_%=:\n\t"
        "mbarrier.try_wait.parity.acquire.cta.shared::cta.b64 P, [%0], %1, 0x989680;\n\t"
        "@P bra.uni WD_%=;\n\t"
        "bra.uni WL_%=;\n\t"
        "WD_%=:\n\t}"
        :: "r"(mbar), "r"(parity) : "memory");
}
__device__ __forceinline__ void bulk_g2s(uint32_t dst, const float* src, uint32_t bytes, uint32_t mbar) {
    asm volatile(
        "cp.async.bulk.shared::cluster.global.mbarrier::complete_tx::bytes [%0], [%1], %2, [%3];"
        :: "r"(dst), "l"(src), "r"(bytes), "r"(mbar) : "memory");
}
__device__ __forceinline__ void mma_tf32(float* c, uint32_t a0, uint32_t a1, uint32_t a2, uint32_t a3,
                                         uint32_t b0, uint32_t b1) {
    asm volatile(
        "mma.sync.aligned.m16n8k8.row.col.f32.tf32.tf32.f32 "
        "{%0,%1,%2,%3}, {%4,%5,%6,%7}, {%8,%9}, {%0,%1,%2,%3};"
        : "+f"(c[0]), "+f"(c[1]), "+f"(c[2]), "+f"(c[3])
        : "r"(a0), "r"(a1), "r"(a2), "r"(a3), "r"(b0), "r"(b1));
}
#define FENCE_ASYNC() asm volatile("fence.proxy.async.shared::cta;" ::: "memory")

__device__ __forceinline__ size_t qbase(int r, int group, int X, int nR) {
    return ((size_t)((group >> 1) * nR + (r >> 7))) * 4096
         + (size_t)((((r & 127) >> 3) * 2 + (group & 1)) * 128 + ((r & 7) * 4 + X) * 4);
}

// ---------------- K0: transpose + tf32-round inputs into atom planes ----------------
__global__ void k0_prep(const float* __restrict__ x,
                        const float* __restrict__ weight,
                        const float* __restrict__ w_right,
                        const float* __restrict__ w_left) {
    int idx = blockIdx.x * blockDim.x + threadIdx.x;   // BATCH*128
    int b = idx >> 7;
    int j = idx & 127;
    int group = j >> 2, X = j & 3;
    int k0v = group * 16 + X;

    float xb[8][4];
    #pragma unroll
    for (int t = 0; t < 4; t++) {
        int k = k0v + 4 * t;
        const float4* p = (const float4*)(x + ((size_t)b * 512 + k) * 8);
        float4 f0 = p[0], f1 = p[1];
        xb[0][t] = f0.x; xb[1][t] = f0.y; xb[2][t] = f0.z; xb[3][t] = f0.w;
        xb[4][t] = f1.x; xb[5][t] = f1.y; xb[6][t] = f1.z; xb[7][t] = f1.w;
    }
    size_t xo = qbase(b, group, X, 16);
    #pragma unroll
    for (int bl = 0; bl < 8; bl++) {
        float4 o = make_float4(rtf(xb[bl][0]), rtf(xb[bl][1]), rtf(xb[bl][2]), rtf(xb[bl][3]));
        *(float4*)(g_XP + (size_t)bl * PLA + xo) = o;
    }

    if (b < NOUT) {
        int m = b;
        size_t wo = qbase(m, group, X, 4);
        float wr[4][4], wl[4][4], wt[20][4];
        #pragma unroll
        for (int t = 0; t < 4; t++) {
            int k = k0v + 4 * t;
            float4 r = ((const float4*)w_right)[(size_t)m * 512 + k];
            wr[0][t] = r.x; wr[1][t] = r.y; wr[2][t] = r.z; wr[3][t] = r.w;
            float4 l = ((const float4*)w_left)[(size_t)m * 512 + k];
            wl[0][t] = l.x; wl[1][t] = l.y; wl[2][t] = l.z; wl[3][t] = l.w;
            const float4* wp = (const float4*)(weight + ((size_t)m * 512 + k) * 20);
            #pragma unroll
            for (int q = 0; q < 5; q++) {
                float4 f = wp[q];
                wt[q*4+0][t] = f.x; wt[q*4+1][t] = f.y; wt[q*4+2][t] = f.z; wt[q*4+3][t] = f.w;
            }
        }
        #pragma unroll
        for (int g = 0; g < 4; g++) {
            float4 o = make_float4(rtf(wr[g][0]), rtf(wr[g][1]), rtf(wr[g][2]), rtf(wr[g][3]));
            *(float4*)(g_WR + (size_t)g * PLB + wo) = o;
            float4 p = make_float4(rtf(wl[g][0]), rtf(wl[g][1]), rtf(wl[g][2]), rtf(wl[g][3]));
            *(float4*)(g_WL + (size_t)g * PLB + wo) = p;
        }
        #pragma unroll
        for (int q = 0; q < 20; q++) {
            float4 o = make_float4(rtf(wt[q][0]), rtf(wt[q][1]), rtf(wt[q][2]), rtf(wt[q][3]));
            *(float4*)(g_WT + (size_t)q * PLB + wo) = o;
        }
    }
}

// ---------------- tensor-core GEMM: 4 warps x (64x64) tiles, bulk ring (R7 order) ----------------
#define STAGE_F 8192                     // A 4096 + B 4096 floats per slot
#define STAGE_BYTES (STAGE_F * 4)
#define SMEM_BYTES (3 * STAGE_BYTES)     // 98304

__global__ void __launch_bounds__(128, 2) gemm_mma(int mode, const float* __restrict__ b_left) {
    extern __shared__ __align__(128) float sm[];
    __shared__ __align__(8) unsigned long long bars[6];   // full0..2, empty0..2

    uint32_t sbase = smem_u32(sm);
    uint32_t barb  = smem_u32(bars);

    int tid = threadIdx.x;
    int z  = c_zord[blockIdx.z];
    int mt = blockIdx.y;
    int nt = blockIdx.x;
    int m0 = mt * 128, n0 = nt * 128;

    int nch = (mode == 0) ? 1 : c_nch[z];
    int n_iter = nch << 4;

    int wid = tid >> 5, lane = tid & 31;
    int rb = (wid >> 1) * 64;     // warp M base (64 rows)
    int cb = (wid & 1) * 64;      // warp N base (64 cols)
    int grp = lane >> 2, tg = lane & 3;

    if (tid == 0) {
        #pragma unroll
        for (int s = 0; s < 3; s++) {
            mbar_init(barb + s * 8, 1);        // full: tx-based
            mbar_init(barb + 24 + s * 8, 4);   // empty: one arrive per warp (4 warps)
        }
        FENCE_ASYNC();
    }
    __syncthreads();

    float acc[4][8][4];
    #pragma unroll
    for (int mi = 0; mi < 4; mi++)
        #pragma unroll
        for (int ni = 0; ni < 8; ni++)
            #pragma unroll
            for (int q = 0; q < 4; q++) acc[mi][ni][q] = 0.f;

    // ---- producer state (tid 0 only) ----
    const float* pA = nullptr;
    const float* pB = nullptr;
    int pch = 0, pq = 0;
    auto setch = [&](int ch) {
        if (mode == 0) {
            pA = g_XP + (size_t)z * PLA;
            pB = g_WR + (size_t)c_grade[z] * PLB;
        } else {
            int ai = c_aidx[z][ch], bi = c_bidx[z][ch];
            pA = (ai < 8) ? g_XP + (size_t)ai * PLA : g_ZP + (size_t)(ai - 8) * PLA;
            pB = (bi < 4) ? g_WL + (size_t)bi * PLB : g_WT + (size_t)(bi - 4) * PLB;
        }
        pA += (size_t)mt * 4096;
        pB += (size_t)nt * 4096;
    };
    auto advance = [&]() {
        pA += 65536;            // next k-chunk: A stride 16 tiles
        pB += 16384;            // next k-chunk: B stride 4 tiles
        if (++pq == 16) { pq = 0; if (++pch < nch) setch(pch); }
    };

    uint32_t pslot = sbase;     // rolling producer slot addr (tracks consumer slot)
    if (tid == 0) {
        setch(0);
        #pragma unroll
        for (int s = 0; s < 3; s++) {
            uint32_t fb = barb + s * 8;
            mbar_expect(fb, 32768);
            bulk_g2s(sbase + s * STAGE_BYTES, pA, 16384, fb);
            bulk_g2s(sbase + s * STAGE_BYTES + 16384, pB, 16384, fb);
            advance();
        }
    }

    const float* cslot = sm;
    int sl = 0, par = 0;        // consumer slot + parity
    int fl = grp * 16 + tg * 4;
    int artA = rb >> 3;         // 0 or 8
    int brt  = cb >> 3;         // 0 or 8

    for (int i = 0; i < n_iter; i++) {
        mbar_wait(barb + sl * 8, par);   // all lanes: try_wait HW-sleeps

        const float* At = cslot;
        const float* Bt = At + 4096;

        #pragma unroll
        for (int kc = 0; kc < 2; kc++) {
            float4 fa[4][2];
            #pragma unroll
            for (int mi = 0; mi < 4; mi++) {
                int ar0 = artA + mi * 2;
                fa[mi][0] = *(const float4*)(At + (ar0 * 2 + kc) * 128 + fl);
                fa[mi][1] = *(const float4*)(At + ((ar0 + 1) * 2 + kc) * 128 + fl);
            }
            float4 fb[8];
            #pragma unroll
            for (int ni = 0; ni < 8; ni++)
                fb[ni] = *(const float4*)(Bt + ((brt + ni) * 2 + kc) * 128 + fl);
            #pragma unroll
            for (int mi = 0; mi < 4; mi++)
                #pragma unroll
                for (int ni = 0; ni < 8; ni++) {
                    mma_tf32(acc[mi][ni],
                             __float_as_uint(fa[mi][0].x), __float_as_uint(fa[mi][1].x),
                             __float_as_uint(fa[mi][0].y), __float_as_uint(fa[mi][1].y),
                             __float_as_uint(fb[ni].x), __float_as_uint(fb[ni].y));
                    mma_tf32(acc[mi][ni],
                             __float_as_uint(fa[mi][0].z), __float_as_uint(fa[mi][1].z),
                             __float_as_uint(fa[mi][0].w), __float_as_uint(fa[mi][1].w),
                             __float_as_uint(fb[ni].z), __float_as_uint(fb[ni].w));
                }
        }

        __syncwarp();
        if (lane == 0) mbar_arrive(barb + 24 + sl * 8);   // empty[sl]

        // refill consumed slot with stage i+3 (R7 ordering: after compute)
        if (tid == 0 && i + 3 < n_iter) {
            mbar_wait(barb + 24 + sl * 8, par);           // all warps done with sl
            uint32_t fb = barb + sl * 8;
            mbar_expect(fb, 32768);
            bulk_g2s(pslot, pA, 16384, fb);
            bulk_g2s(pslot + 16384, pB, 16384, fb);
            advance();
        }

        // roll
        cslot += STAGE_F;
        pslot += STAGE_BYTES;
        if (++sl == 3) { sl = 0; par ^= 1; cslot = sm; pslot = sbase; }
    }

    // ---------------- epilogue ----------------
    const float RS2 = 0.70710678118654752440f;
    if (mode == 0) {
        // stage output tile (128x128, atom layout) in smem, then contiguous copy-out
        __syncthreads();
        #pragma unroll
        for (int mi = 0; mi < 4; mi++)
            #pragma unroll
            for (int h = 0; h < 2; h++) {
                int r = rb + mi * 16 + grp + h * 8;          // 0..127
                int rpart = ((r >> 3) * 2) * 128 + (r & 7) * 16;
                #pragma unroll
                for (int ni = 0; ni < 8; ni++) {
                    int c = cb + ni * 8 + 2 * tg;            // 0..126
                    #pragma unroll
                    for (int d = 0; d < 2; d++) {
                        int cc = c + d;
                        int off = (cc >> 5) * 4096 + rpart + ((cc >> 4) & 1) * 128
                                + (cc & 3) * 4 + ((cc >> 2) & 3);
                        sm[off] = acc[mi][ni][h * 2 + d];
                    }
                }
            }
        __syncthreads();
        float* XRp = g_XR + (size_t)z * PLA + ((size_t)(nt * 4) * 16 + mt) * 4096;
        #pragma unroll
        for (int t = 0; t < 4; t++) {
            float* dst = XRp + (size_t)t * 65536;
            const float* src = sm + t * 4096;
            #pragma unroll
            for (int r = 0; r < 8; r++) {
                int e = tid + (r << 7);                      // 128 threads x 8 = 1024 chunks
                *(float4*)(dst + e * 4) = *(const float4*)(src + e * 4);
            }
        }
    } else {
        float* Out = g_OUTP + (size_t)z * PLA;
        #pragma unroll
        for (int mi = 0; mi < 4; mi++)
            #pragma unroll
            for (int h = 0; h < 2; h++) {
                int row = m0 + rb + mi * 16 + grp + h * 8;
                float* dp = Out + (size_t)row * NOUT + n0 + cb;
                #pragma unroll
                for (int ni = 0; ni < 8; ni++) {
                    int col = ni * 8 + 2 * tg;
                    float v0 = acc[mi][ni][h * 2 + 0];
                    float v1 = acc[mi][ni][h * 2 + 1];
                    if (z == 0) {
                        v0 += b_left[n0 + cb + col];
                        v1 += b_left[n0 + cb + col + 1];
                    }
                    *(float2*)(dp + col) = make_float2(v0 * RS2, v1 * RS2);
                }
            }
    }
}

// ---------------- K2: gating + 44 pair channels (atom quads in/out) ----------------
__global__ void k2_pair(const float* __restrict__ norm_a) {
    int idx = blockIdx.x * blockDim.x + threadIdx.x;   // BATCH*128
    int b = idx >> 7;
    int j = idx & 127;
    int group = j >> 2, X = j & 3;
    int k0v = group * 16 + X;

    size_t qo = qbase(b, group, X, 16);
    float xv[8][4], yv[8][4];
    #pragma unroll
    for (int bl = 0; bl < 8; bl++) {
        float4 fx = *(const float4*)(g_XP + (size_t)bl * PLA + qo);
        xv[bl][0] = fx.x; xv[bl][1] = fx.y; xv[bl][2] = fx.z; xv[bl][3] = fx.w;
        float4 fy = *(const float4*)(g_XR + (size_t)bl * PLA + qo);
        yv[bl][0] = fy.x; yv[bl][1] = fy.y; yv[bl][2] = fy.z; yv[bl][3] = fy.w;
    }

    #pragma unroll
    for (int t = 0; t < 4; t++) {
        int n = k0v + 4 * t;
        float4 na = *(const float4*)(norm_a + n * 4);
        float n0 = fabsf(yv[0][t]);
        float n1 = sqrtf(yv[1][t]*yv[1][t] + yv[2][t]*yv[2][t] + yv[3][t]*yv[3][t]);
        float n2 = sqrtf(yv[4][t]*yv[4][t] + yv[5][t]*yv[5][t] + yv[6][t]*yv[6][t]);
        float n3 = fabsf(yv[7][t]);
        float s0 = 1.f / (1.f + expf(-na.x));
        float s1 = 1.f / (1.f + expf(-na.y));
        float s2 = 1.f / (1.f + expf(-na.z));
        float s3 = 1.f / (1.f + expf(-na.w));
        float i0 = 1.f / (s0 * (n0 - 1.f) + 1.f + 1e-6f);
        float i1 = 1.f / (s1 * (n1 - 1.f) + 1.f + 1e-6f);
        float i2 = 1.f / (s2 * (n2 - 1.f) + 1.f + 1e-6f);
        float i3 = 1.f / (s3 * (n3 - 1.f) + 1.f + 1e-6f);
        yv[0][t] *= i0;
        yv[1][t] *= i1; yv[2][t] *= i1; yv[3][t] *= i1;
        yv[4][t] *= i2; yv[5][t] *= i2; yv[6][t] *= i2;
        yv[7][t] *= i3;
    }

    auto emit = [&](int c, auto f) {
        float4 o = make_float4(rtf(f(0)), rtf(f(1)), rtf(f(2)), rtf(f(3)));
        *(float4*)(g_ZP + (size_t)c * PLA + qo) = o;
    };
    emit(0,  [&](int t){ return xv[0][t]*yv[0][t]; });
    emit(1,  [&](int t){ return xv[0][t]*yv[1][t]; });
    emit(2,  [&](int t){ return xv[0][t]*yv[2][t]; });
    emit(3,  [&](int t){ return xv[0][t]*yv[3][t]; });
    emit(4,  [&](int t){ return xv[0][t]*yv[4][t]; });
    emit(5,  [&](int t){ return xv[0][t]*yv[5][t]; });
    emit(6,  [&](int t){ return xv[0][t]*yv[6][t]; });
    emit(7,  [&](int t){ return xv[0][t]*yv[7][t]; });
    emit(8,  [&](int t){ return xv[1][t]*yv[1][t] + xv[2][t]*yv[2][t] + xv[3][t]*yv[3][t]; });
    emit(9,  [&](int t){ return xv[1][t]*yv[0][t]; });
    emit(10, [&](int t){ return xv[2][t]*yv[0][t]; });
    emit(11, [&](int t){ return xv[3][t]*yv[0][t]; });
    emit(12, [&](int t){ return -xv[2][t]*yv[4][t] - xv[3][t]*yv[5][t]; });
    emit(13, [&](int t){ return  xv[1][t]*yv[4][t] - xv[3][t]*yv[6][t]; });
    emit(14, [&](int t){ return  xv[1][t]*yv[5][t] + xv[2][t]*yv[6][t]; });
    emit(15, [&](int t){ return  xv[1][t]*yv[2][t] - xv[2][t]*yv[1][t]; });
    emit(16, [&](int t){ return  xv[1][t]*yv[3][t] - xv[3][t]*yv[1][t]; });
    emit(17, [&](int t){ return  xv[2][t]*yv[3][t] - xv[3][t]*yv[2][t]; });
    emit(18, [&](int t){ return  xv[3][t]*yv[7][t]; });
    emit(19, [&](int t){ return -xv[2][t]*yv[7][t]; });
    emit(20, [&](int t){ return  xv[1][t]*yv[7][t]; });
    emit(21, [&](int t){ return  xv[1][t]*yv[6][t] - xv[2][t]*yv[5][t] + xv[3][t]*yv[4][t]; });
    emit(22, [&](int t){ return -(xv[4][t]*yv[4][t] + xv[5][t]*yv[5][t] + xv[6][t]*yv[6][t]); });
    emit(23, [&](int t){ return  xv[4][t]*yv[2][t] + xv[5][t]*yv[3][t]; });
    emit(24, [&](int t){ return -xv[4][t]*yv[1][t] + xv[6][t]*yv[3][t]; });
    emit(25, [&](int t){ return -xv[5][t]*yv[1][t] - xv[6][t]*yv[2][t]; });
    emit(26, [&](int t){ return -xv[6][t]*yv[7][t]; });
    emit(27, [&](int t){ return  xv[5][t]*yv[7][t]; });
    emit(28, [&](int t){ return -xv[4][t]*yv[7][t]; });
    emit(29, [&](int t){ return  xv[4][t]*yv[0][t]; });
    emit(30, [&](int t){ return  xv[5][t]*yv[0][t]; });
    emit(31, [&](int t){ return  xv[6][t]*yv[0][t]; });
    emit(32, [&](int t){ return -xv[5][t]*yv[6][t] + xv[6][t]*yv[5][t]; });
    emit(33, [&](int t){ return  xv[4][t]*yv[6][t] - xv[6][t]*yv[4][t]; });
    emit(34, [&](int t){ return -xv[4][t]*yv[5][t] + xv[5][t]*yv[4][t]; });
    emit(35, [&](int t){ return  xv[4][t]*yv[3][t] - xv[5][t]*yv[2][t] + xv[6][t]*yv[1][t]; });
    emit(36, [&](int t){ return -xv[7][t]*yv[7][t]; });
    emit(37, [&](int t){ return -xv[7][t]*yv[6][t]; });
    emit(38, [&](int t){ return  xv[7][t]*yv[5][t]; });
    emit(39, [&](int t){ return -xv[7][t]*yv[4][t]; });
    emit(40, [&](int t){ return  xv[7][t]*yv[3][t]; });
    emit(41, [&](int t){ return -xv[7][t]*yv[2][t]; });
    emit(42, [&](int t){ return  xv[7][t]*yv[1][t]; });
    emit(43, [&](int t){ return  xv[7][t]*yv[0][t]; });
}

// ---------------- K4: planar -> interleaved output ----------------
__global__ void k4_out(float* __restrict__ out) {
    int idx = blockIdx.x * blockDim.x + threadIdx.x;   // BATCH*NOUT
    size_t o = (size_t)idx;
    float4 o0, o1;
    o0.x = g_OUTP[0*PLA + o]; o0.y = g_OUTP[1*PLA + o];
    o0.z = g_OUTP[2*PLA + o]; o0.w = g_OUTP[3*PLA + o];
    o1.x = g_OUTP[4*PLA + o]; o1.y = g_OUTP[5*PLA + o];
    o1.z = g_OUTP[6*PLA + o]; o1.w = g_OUTP[7*PLA + o];
    ((float4*)out)[o * 2 + 0] = o0;
    ((float4*)out)[o * 2 + 1] = o1;
}

// ---------------- launch ----------------
extern "C" void kernel_launch(void* const* d_in, const int* in_sizes, int n_in,
                              void* d_out, int out_size) {
    const float* x       = (const float*)d_in[0];
    const float* weight  = (const float*)d_in[1];
    const float* w_right = (const float*)d_in[2];
    const float* w_left  = (const float*)d_in[3];
    const float* b_left  = (const float*)d_in[4];
    const float* norm_a  = (const float*)d_in[5];
    float* out = (float*)d_out;

    cudaFuncSetAttribute(gemm_mma, cudaFuncAttributeMaxDynamicSharedMemorySize, SMEM_BYTES);

    int eb = (BATCH * 128) / 256;
    k0_prep<<<eb, 256>>>(x, weight, w_right, w_left);

    dim3 gg(NOUT / 128, BATCH / 128, 8);
    gemm_mma<<<gg, 128, SMEM_BYTES>>>(0, nullptr);
    k2_pair<<<eb, 256>>>(norm_a);
    gemm_mma<<<gg, 128, SMEM_BYTES>>>(1, b_left);
    k4_out<<<(BATCH * NOUT) / 256, 256>>>(out);
}